// round 9
// baseline (speedup 1.0000x reference)
#include <cuda_runtime.h>

#define MAXN 100000
#define EMAX 6400000
#define SCAN_CHUNK 2048   // 512 threads x int4
#define MAXBLK 64

// Static scratch
__device__ float  d_x8[MAXN * 8];       // x padded to 8 (32B rows)
__device__ float  d_agg1[MAXN * 8];     // x + sum x[src]
__device__ float  d_g[MAXN * 32];       // g = h_A @ w1b (128B rows)
__device__ int    d_deg[MAXN + 4];      // zero at entry of every call
__device__ int    d_off[MAXN + 8];      // exclusive prefix; d_off[N] = E
__device__ int    d_rank[EMAX];         // edge's rank within its dst bucket
__device__ int    d_srcs[EMAX];         // CSR: sources grouped by dst
__device__ int    d_incl[MAXBLK];       // lookback: inclusive block prefix
__device__ int    d_flag[MAXBLK];       // lookback: ready flags
__device__ float2 d_sc[MAXN];

// kH: histogram of dst + per-edge rank; also x8 init and flag zeroing. 2 edges/thread.
__global__ void __launch_bounds__(256) kH_hist(const int* __restrict__ ei,
                                               const float* __restrict__ x,
                                               int E, int N) {
    int t = blockIdx.x * blockDim.x + threadIdx.x;
    if (t < MAXBLK) d_flag[t] = 0;
    if (t < N) {   // x8 init
        const float* xr = x + (size_t)t * 7;
        float4 lo = make_float4(__ldg(xr), __ldg(xr + 1), __ldg(xr + 2), __ldg(xr + 3));
        float4 hi = make_float4(__ldg(xr + 4), __ldg(xr + 5), __ldg(xr + 6), 0.f);
        ((float4*)(d_x8 + (size_t)t * 8))[0] = lo;
        ((float4*)(d_x8 + (size_t)t * 8))[1] = hi;
    }
    int e0 = 2 * t;
    if (e0 + 1 < E) {
        int2 d = *(const int2*)(ei + E + e0);
        int r0 = atomicAdd(&d_deg[d.x], 1);
        int r1 = atomicAdd(&d_deg[d.y], 1);
        *(int2*)(d_rank + e0) = make_int2(r0, r1);
    } else if (e0 < E) {
        int d = __ldg(ei + E + e0);
        d_rank[e0] = atomicAdd(&d_deg[d], 1);
    }
}

// kScan: single-kernel decoupled-lookback exclusive scan of d_deg -> d_off
__global__ void __launch_bounds__(512) kScan(int N, int NB) {
    __shared__ int s_w[16];
    __shared__ int s_prev;
    int tid = threadIdx.x, lane = tid & 31, wid = tid >> 5;
    int b = blockIdx.x;
    int base = b * SCAN_CHUNK + tid * 4;
    int4 v = make_int4(0, 0, 0, 0);
    if (base < N) v = *(const int4*)(d_deg + base);
    int t1 = v.x + v.y, t2 = t1 + v.z, tot = t2 + v.w;
    int scan = tot;
#pragma unroll
    for (int o = 1; o < 32; o <<= 1) {
        int nv = __shfl_up_sync(~0u, scan, o);
        if (lane >= o) scan += nv;
    }
    if (lane == 31) s_w[wid] = scan;
    __syncthreads();
    if (wid == 0 && lane < 16) {
        int w = s_w[lane];
#pragma unroll
        for (int o = 1; o < 16; o <<= 1) {
            int nv = __shfl_up_sync(0xffffu, w, o);
            if (lane >= o) w += nv;
        }
        s_w[lane] = w;
    }
    __syncthreads();
    int btot = s_w[15];
    if (tid == 0) {
        int prev = 0;
        if (b > 0) {
            while (((volatile int*)d_flag)[b - 1] == 0) {}
            __threadfence();
            prev = ((volatile int*)d_incl)[b - 1];
        }
        d_incl[b] = prev + btot;
        __threadfence();
        ((volatile int*)d_flag)[b] = 1;
        s_prev = prev;
        if (b == NB - 1) d_off[N] = prev + btot;
    }
    __syncthreads();
    int excl = scan - tot + (wid > 0 ? s_w[wid - 1] : 0) + s_prev;
    if (base < N)
        *(int4*)(d_off + base) = make_int4(excl, excl + v.x, excl + t1, excl + t2);
}

// kP: place srcs into CSR (no atomics); re-zero d_deg for the next call. 2 edges/thread.
__global__ void __launch_bounds__(256) kP_place(const int* __restrict__ ei, int E, int N) {
    int t = blockIdx.x * blockDim.x + threadIdx.x;
    if (t < N) d_deg[t] = 0;
    int e0 = 2 * t;
    if (e0 + 1 < E) {
        int2 s = *(const int2*)(ei + e0);
        int2 d = *(const int2*)(ei + E + e0);
        int2 r = *(const int2*)(d_rank + e0);
        d_srcs[__ldg(d_off + d.x) + r.x] = s.x;
        d_srcs[__ldg(d_off + d.y) + r.y] = s.y;
    } else if (e0 < E) {
        d_srcs[__ldg(d_off + __ldg(ei + E + e0)) + d_rank[e0]] = __ldg(ei + e0);
    }
}

// kE: agg1[n] = x8[n] + sum x8[src].  8 lanes/node, 4 nodes/warp.
__global__ void __launch_bounds__(256) kE_agg1(int N) {
    int tid = blockIdx.x * blockDim.x + threadIdx.x;
    int node = tid >> 3;
    int j = tid & 7;
    if (node >= N) return;
    int beg = __ldg(d_off + node), end = __ldg(d_off + node + 1);
    float acc = d_x8[(size_t)node * 8 + j];
    int i = beg;
    for (; i + 1 < end; i += 2) {
        int s0 = __ldg(d_srcs + i);
        int s1 = __ldg(d_srcs + i + 1);
        acc += __ldg(d_x8 + (size_t)s0 * 8 + j);
        acc += __ldg(d_x8 + (size_t)s1 * 8 + j);
    }
    if (i < end) acc += __ldg(d_x8 + (size_t)__ldg(d_srcs + i) * 8 + j);
    d_agg1[(size_t)node * 8 + j] = acc;
}

// k2: per node: t[7] -> relu(t@w1a+b1a) -> @w2a+b2a -> relu -> @w1b = g[32]
__global__ void __launch_bounds__(128) k2_mlpA(
    const float* __restrict__ w1a, const float* __restrict__ b1a,
    const float* __restrict__ w2a, const float* __restrict__ b2a,
    const float* __restrict__ w1b, int N) {
    __shared__ float s_w1a[7 * 64];
    __shared__ float s_b1a[64];
    __shared__ float s_w2a[64 * 64];
    __shared__ float s_b2a[64];
    __shared__ float s_w1b[64 * 32];
    for (int i = threadIdx.x; i < 112; i += 128)
        ((float4*)s_w1a)[i] = __ldg((const float4*)w1a + i);
    if (threadIdx.x < 64) { s_b1a[threadIdx.x] = b1a[threadIdx.x]; s_b2a[threadIdx.x] = b2a[threadIdx.x]; }
    for (int i = threadIdx.x; i < 1024; i += 128)
        ((float4*)s_w2a)[i] = __ldg((const float4*)w2a + i);
    for (int i = threadIdx.x; i < 512; i += 128)
        ((float4*)s_w1b)[i] = __ldg((const float4*)w1b + i);
    __syncthreads();

    int n = blockIdx.x * 128 + threadIdx.x;
    if (n >= N) return;

    float tin[7];
    const float* tr = d_agg1 + (size_t)n * 8;
#pragma unroll
    for (int i = 0; i < 7; i++) tin[i] = tr[i];

    float acc[64];
#pragma unroll
    for (int j = 0; j < 64; j++) acc[j] = 0.f;
#pragma unroll 1
    for (int k = 0; k < 64; k++) {
        float h = s_b1a[k];
#pragma unroll
        for (int i = 0; i < 7; i++) h = fmaf(tin[i], s_w1a[i * 64 + k], h);
        h = fmaxf(h, 0.f);
#pragma unroll
        for (int j = 0; j < 64; j++) acc[j] = fmaf(h, s_w2a[k * 64 + j], acc[j]);
    }

    float g[32];
#pragma unroll
    for (int j = 0; j < 32; j++) g[j] = 0.f;
#pragma unroll 1
    for (int k = 0; k < 64; k++) {
        float h = fmaxf(acc[k] + s_b2a[k], 0.f);
#pragma unroll
        for (int j = 0; j < 32; j++) g[j] = fmaf(h, s_w1b[k * 32 + j], g[j]);
    }

    float4* gout = (float4*)(d_g + (size_t)n * 32);
#pragma unroll
    for (int q = 0; q < 8; q++)
        gout[q] = make_float4(g[4 * q], g[4 * q + 1], g[4 * q + 2], g[4 * q + 3]);
}

// kF: warp/node: agg2 = g[n] + sum g[src] (4 groups x 8 lanes x float4), fused mlpB + score
__global__ void __launch_bounds__(256) kF_agg2_mlpB(
    const float* __restrict__ b1b, const float* __restrict__ w2b,
    const float* __restrict__ b2b, const float* __restrict__ ws, int N) {
    __shared__ float s_w2b[32 * 32];
    ((float4*)s_w2b)[threadIdx.x] = __ldg((const float4*)w2b + threadIdx.x);
    __syncthreads();

    int lane = threadIdx.x & 31;
    int grp = lane >> 3;
    int j = lane & 7;
    int node = blockIdx.x * 8 + (threadIdx.x >> 5);
    if (node >= N) return;

    int beg = __ldg(d_off + node), end = __ldg(d_off + node + 1);
    float4 acc = make_float4(0.f, 0.f, 0.f, 0.f);
    if (grp == 0) acc = __ldg((const float4*)(d_g + (size_t)node * 32) + j);
#pragma unroll 2
    for (int i = beg + grp; i < end; i += 4) {
        int s = __ldg(d_srcs + i);
        float4 v = __ldg((const float4*)(d_g + (size_t)s * 32) + j);
        acc.x += v.x; acc.y += v.y; acc.z += v.z; acc.w += v.w;
    }
    // reduce across 4 groups (lanes l, l^8, l^16, l^24 hold same dims)
#pragma unroll
    for (int o = 8; o <= 16; o <<= 1) {
        acc.x += __shfl_xor_sync(~0u, acc.x, o);
        acc.y += __shfl_xor_sync(~0u, acc.y, o);
        acc.z += __shfl_xor_sync(~0u, acc.z, o);
        acc.w += __shfl_xor_sync(~0u, acc.w, o);
    }
    float4 bb = __ldg((const float4*)b1b + j);
    float4 a4;
    a4.x = fmaxf(acc.x + bb.x, 0.f);
    a4.y = fmaxf(acc.y + bb.y, 0.f);
    a4.z = fmaxf(acc.z + bb.z, 0.f);
    a4.w = fmaxf(acc.w + bb.w, 0.f);

    // h2[lane] = b2b[lane] + sum_k a[k] * w2b[k*32+lane]
    float h2 = __ldg(b2b + lane);
#pragma unroll
    for (int jj = 0; jj < 8; jj++) {
        float a0 = __shfl_sync(~0u, a4.x, jj);
        float a1 = __shfl_sync(~0u, a4.y, jj);
        float a2 = __shfl_sync(~0u, a4.z, jj);
        float a3 = __shfl_sync(~0u, a4.w, jj);
        h2 = fmaf(a0, s_w2b[(4 * jj + 0) * 32 + lane], h2);
        h2 = fmaf(a1, s_w2b[(4 * jj + 1) * 32 + lane], h2);
        h2 = fmaf(a2, s_w2b[(4 * jj + 2) * 32 + lane], h2);
        h2 = fmaf(a3, s_w2b[(4 * jj + 3) * 32 + lane], h2);
    }
    float s0 = h2 * __ldg(ws + lane);
    float s1 = h2 * __ldg(ws + 32 + lane);
#pragma unroll
    for (int o = 16; o > 0; o >>= 1) {
        s0 += __shfl_down_sync(~0u, s0, o);
        s1 += __shfl_down_sync(~0u, s1, o);
    }
    if (lane == 0) d_sc[node] = make_float2(s0, s1);
}

// k5: out[i] = sigmoid(s0[c0] + s1[c1] + bs).  2 candidates per thread.
__global__ void k5_score(const int* __restrict__ cand, const float* __restrict__ bs,
                         float* __restrict__ out, int C) {
    int i = blockIdx.x * blockDim.x + threadIdx.x;
    int npair = C >> 1;
    float b = __ldg(bs);
    if (i < npair) {
        int4 c = __ldg((const int4*)cand + i);
        float z0 = d_sc[c.x].x + d_sc[c.y].y + b;
        float z1 = d_sc[c.z].x + d_sc[c.w].y + b;
        ((float2*)out)[i] = make_float2(1.f / (1.f + __expf(-z0)),
                                        1.f / (1.f + __expf(-z1)));
    }
    if ((C & 1) && i == 0) {
        int2 ce = __ldg((const int2*)cand + (C - 1));
        float z = d_sc[ce.x].x + d_sc[ce.y].y + b;
        out[C - 1] = 1.f / (1.f + __expf(-z));
    }
}

extern "C" void kernel_launch(void* const* d_in, const int* in_sizes, int n_in,
                              void* d_out, int out_size) {
    const float* x    = (const float*)d_in[0];
    const int*   ei   = (const int*)d_in[1];
    const int*   cand = (const int*)d_in[2];
    const float* w1a = (const float*)d_in[3];
    const float* b1a = (const float*)d_in[4];
    const float* w2a = (const float*)d_in[5];
    const float* b2a = (const float*)d_in[6];
    const float* w1b = (const float*)d_in[7];
    const float* b1b = (const float*)d_in[8];
    const float* w2b = (const float*)d_in[9];
    const float* b2b = (const float*)d_in[10];
    const float* ws  = (const float*)d_in[11];
    const float* bs  = (const float*)d_in[12];

    int N = in_sizes[0] / 7;
    int E = in_sizes[1] / 2;
    int C = in_sizes[2] / 2;
    float* out = (float*)d_out;
    int NB = (N + SCAN_CHUNK - 1) / SCAN_CHUNK;
    int halfE = (E + 1) / 2;

    kH_hist <<<(halfE + 255) / 256, 256>>>(ei, x, E, N);
    kScan   <<<NB, 512>>>(N, NB);
    kP_place<<<(halfE + 255) / 256, 256>>>(ei, E, N);
    kE_agg1 <<<(N * 8 + 255) / 256, 256>>>(N);
    k2_mlpA <<<(N + 127) / 128, 128>>>(w1a, b1a, w2a, b2a, w1b, N);
    kF_agg2_mlpB<<<(N + 7) / 8, 256>>>(b1b, w2b, b2b, ws, N);
    k5_score<<<((C >> 1) + 255) / 256, 256>>>(cand, bs, out, C);
}

// round 10
// speedup vs baseline: 1.2104x; 1.2104x over previous
#include <cuda_runtime.h>
#include <cuda_fp16.h>

#define MAXN 100000
#define EMAX 6400000
#define SCAN_CHUNK 2048   // 512 threads x int4
#define MAXBLK 64

// Static scratch
__device__ float  d_x8[MAXN * 8];     // x padded to 8 (32B rows)
__device__ float  d_agg1[MAXN * 8];   // x + sum x[src]
__device__ __half d_g2[MAXN * 32];    // g = h_A @ w1b, fp16 (64B rows)
__device__ int    d_deg[MAXN];
__device__ int    d_off[MAXN + 4];    // exclusive prefix; d_off[N] = E
__device__ int    d_rank[EMAX];       // edge's rank within its dst bucket
__device__ int    d_srcs[EMAX];       // CSR: sources grouped by dst
__device__ int    d_bsum[MAXBLK];
__device__ int    d_boff[MAXBLK];
__device__ float2 d_sc[MAXN];

// kA: pad x into d_x8, zero deg
__global__ void kA_init(const float* __restrict__ x, int N) {
    int n = blockIdx.x * blockDim.x + threadIdx.x;
    if (n >= N) return;
    const float* xr = x + (size_t)n * 7;
    float4 lo = make_float4(__ldg(xr), __ldg(xr + 1), __ldg(xr + 2), __ldg(xr + 3));
    float4 hi = make_float4(__ldg(xr + 4), __ldg(xr + 5), __ldg(xr + 6), 0.f);
    ((float4*)(d_x8 + (size_t)n * 8))[0] = lo;
    ((float4*)(d_x8 + (size_t)n * 8))[1] = hi;
    d_deg[n] = 0;
}

// kH: histogram + per-edge rank (coalesced store), 1 edge/thread
__global__ void kH_hist(const int* __restrict__ ei, int E) {
    int e = blockIdx.x * blockDim.x + threadIdx.x;
    if (e >= E) return;
    int d = __ldg(ei + E + e);
    d_rank[e] = atomicAdd(&d_deg[d], 1);
}

// kS1: per-block sums of deg
__global__ void __launch_bounds__(512) kS1(int N) {
    __shared__ int s_w[16];
    int tid = threadIdx.x;
    int base = blockIdx.x * SCAN_CHUNK + tid * 4;
    int4 v = make_int4(0, 0, 0, 0);
    if (base < N) v = *(const int4*)(d_deg + base);
    int sum = v.x + v.y + v.z + v.w;
#pragma unroll
    for (int o = 16; o > 0; o >>= 1) sum += __shfl_down_sync(~0u, sum, o);
    if ((tid & 31) == 0) s_w[tid >> 5] = sum;
    __syncthreads();
    if (tid < 16) {
        int t = s_w[tid];
#pragma unroll
        for (int o = 8; o > 0; o >>= 1) t += __shfl_down_sync(0xffffu, t, o);
        if (tid == 0) d_bsum[blockIdx.x] = t;
    }
}

// kS2: serial scan of block sums (NB <= 64)
__global__ void kS2(int NB, int N) {
    int run = 0;
    for (int b = 0; b < NB; b++) { d_boff[b] = run; run += d_bsum[b]; }
    d_off[N] = run;
}

// kS3: block-level exclusive scan + global offset -> d_off
__global__ void __launch_bounds__(512) kS3(int N) {
    __shared__ int s_w[16];
    int tid = threadIdx.x;
    int lane = tid & 31, wid = tid >> 5;
    int base = blockIdx.x * SCAN_CHUNK + tid * 4;
    int4 v = make_int4(0, 0, 0, 0);
    if (base < N) v = *(const int4*)(d_deg + base);
    int t1 = v.x + v.y, t2 = t1 + v.z, tot = t2 + v.w;
    int scan = tot;
#pragma unroll
    for (int o = 1; o < 32; o <<= 1) {
        int nv = __shfl_up_sync(~0u, scan, o);
        if (lane >= o) scan += nv;
    }
    if (lane == 31) s_w[wid] = scan;
    __syncthreads();
    if (wid == 0 && lane < 16) {
        int w = s_w[lane];
#pragma unroll
        for (int o = 1; o < 16; o <<= 1) {
            int nv = __shfl_up_sync(0xffffu, w, o);
            if (lane >= o) w += nv;
        }
        s_w[lane] = w;
    }
    __syncthreads();
    int excl = scan - tot + (wid > 0 ? s_w[wid - 1] : 0) + d_boff[blockIdx.x];
    if (base < N)
        *(int4*)(d_off + base) = make_int4(excl, excl + v.x, excl + t1, excl + t2);
}

// kP: place srcs into CSR (no atomics), 1 edge/thread
__global__ void kP_place(const int* __restrict__ ei, int E) {
    int e = blockIdx.x * blockDim.x + threadIdx.x;
    if (e >= E) return;
    int s = __ldg(ei + e);
    int d = __ldg(ei + E + e);
    d_srcs[__ldg(d_off + d) + d_rank[e]] = s;
}

// kE: agg1[n] = x8[n] + sum x8[src].  8 lanes/node, 4 nodes/warp.
__global__ void __launch_bounds__(256) kE_agg1(int N) {
    int tid = blockIdx.x * blockDim.x + threadIdx.x;
    int node = tid >> 3;
    int j = tid & 7;
    if (node >= N) return;
    int beg = __ldg(d_off + node), end = __ldg(d_off + node + 1);
    float acc = d_x8[(size_t)node * 8 + j];
    int i = beg;
    for (; i + 1 < end; i += 2) {
        int s0 = __ldg(d_srcs + i);
        int s1 = __ldg(d_srcs + i + 1);
        acc += __ldg(d_x8 + (size_t)s0 * 8 + j);
        acc += __ldg(d_x8 + (size_t)s1 * 8 + j);
    }
    if (i < end) acc += __ldg(d_x8 + (size_t)__ldg(d_srcs + i) * 8 + j);
    d_agg1[(size_t)node * 8 + j] = acc;
}

// k2: per node: t[7] -> relu(t@w1a+b1a) -> @w2a+b2a -> relu -> @w1b = g[32] (fp16 out)
__global__ void __launch_bounds__(128) k2_mlpA(
    const float* __restrict__ w1a, const float* __restrict__ b1a,
    const float* __restrict__ w2a, const float* __restrict__ b2a,
    const float* __restrict__ w1b, int N) {
    __shared__ float s_w1a[7 * 64];
    __shared__ float s_b1a[64];
    __shared__ float s_w2a[64 * 64];
    __shared__ float s_b2a[64];
    __shared__ float s_w1b[64 * 32];
    for (int i = threadIdx.x; i < 112; i += 128)
        ((float4*)s_w1a)[i] = __ldg((const float4*)w1a + i);
    if (threadIdx.x < 64) { s_b1a[threadIdx.x] = b1a[threadIdx.x]; s_b2a[threadIdx.x] = b2a[threadIdx.x]; }
    for (int i = threadIdx.x; i < 1024; i += 128)
        ((float4*)s_w2a)[i] = __ldg((const float4*)w2a + i);
    for (int i = threadIdx.x; i < 512; i += 128)
        ((float4*)s_w1b)[i] = __ldg((const float4*)w1b + i);
    __syncthreads();

    int n = blockIdx.x * 128 + threadIdx.x;
    if (n >= N) return;

    float tin[7];
    const float* tr = d_agg1 + (size_t)n * 8;
#pragma unroll
    for (int i = 0; i < 7; i++) tin[i] = tr[i];

    float acc[64];
#pragma unroll
    for (int j = 0; j < 64; j++) acc[j] = 0.f;
#pragma unroll 1
    for (int k = 0; k < 64; k++) {
        float h = s_b1a[k];
#pragma unroll
        for (int i = 0; i < 7; i++) h = fmaf(tin[i], s_w1a[i * 64 + k], h);
        h = fmaxf(h, 0.f);
#pragma unroll
        for (int j = 0; j < 64; j++) acc[j] = fmaf(h, s_w2a[k * 64 + j], acc[j]);
    }

    float g[32];
#pragma unroll
    for (int j = 0; j < 32; j++) g[j] = 0.f;
#pragma unroll 1
    for (int k = 0; k < 64; k++) {
        float h = fmaxf(acc[k] + s_b2a[k], 0.f);
#pragma unroll
        for (int j = 0; j < 32; j++) g[j] = fmaf(h, s_w1b[k * 32 + j], g[j]);
    }

    half2 t16[16];
#pragma unroll
    for (int i = 0; i < 16; i++) t16[i] = __floats2half2_rn(g[2 * i], g[2 * i + 1]);
    uint4* dst = (uint4*)(d_g2 + (size_t)n * 32);
#pragma unroll
    for (int q = 0; q < 4; q++) dst[q] = ((uint4*)t16)[q];
}

// kF: warp/node: agg2 = g[n] + sum g[src].  fp16 rows (64B), 4 groups x 8 lanes x uint2.
// Accumulate fp32; then fused mlpB + score scalars (same epilogue as R7).
__global__ void __launch_bounds__(256) kF_agg2_mlpB(
    const float* __restrict__ b1b, const float* __restrict__ w2b,
    const float* __restrict__ b2b, const float* __restrict__ ws, int N) {
    __shared__ float s_w2b[32 * 32];
    ((float4*)s_w2b)[threadIdx.x] = __ldg((const float4*)w2b + threadIdx.x);
    __syncthreads();

    int lane = threadIdx.x & 31;
    int grp = lane >> 3;          // 4 groups; each group covers one src row per step
    int j = lane & 7;             // uint2 slot -> dims [4j, 4j+4)
    int node = blockIdx.x * 8 + (threadIdx.x >> 5);
    if (node >= N) return;

    int beg = __ldg(d_off + node), end = __ldg(d_off + node + 1);
    float a0 = 0.f, a1 = 0.f, a2 = 0.f, a3 = 0.f;

    if (grp == 0) {   // self term
        uint2 r = *(const uint2*)(d_g2 + (size_t)node * 32 + j * 4);
        float2 f0 = __half22float2(*(const half2*)&r.x);
        float2 f1 = __half22float2(*(const half2*)&r.y);
        a0 += f0.x; a1 += f0.y; a2 += f1.x; a3 += f1.y;
    }
#pragma unroll 2
    for (int i = beg + grp; i < end; i += 4) {
        int s = __ldg(d_srcs + i);
        uint2 r = __ldg((const uint2*)(d_g2 + (size_t)s * 32 + j * 4));
        float2 f0 = __half22float2(*(const half2*)&r.x);
        float2 f1 = __half22float2(*(const half2*)&r.y);
        a0 += f0.x; a1 += f0.y; a2 += f1.x; a3 += f1.y;
    }
    // reduce across 4 groups (lanes l, l^8, l^16, l^24 hold same dims)
#pragma unroll
    for (int o = 8; o <= 16; o <<= 1) {
        a0 += __shfl_xor_sync(~0u, a0, o);
        a1 += __shfl_xor_sync(~0u, a1, o);
        a2 += __shfl_xor_sync(~0u, a2, o);
        a3 += __shfl_xor_sync(~0u, a3, o);
    }
    float4 bb = __ldg((const float4*)b1b + j);
    float4 a4;
    a4.x = fmaxf(a0 + bb.x, 0.f);
    a4.y = fmaxf(a1 + bb.y, 0.f);
    a4.z = fmaxf(a2 + bb.z, 0.f);
    a4.w = fmaxf(a3 + bb.w, 0.f);

    // h2[lane] = b2b[lane] + sum_k a[k] * w2b[k*32+lane];  a[4*jj+m] lives in lane jj
    float h2 = __ldg(b2b + lane);
#pragma unroll
    for (int jj = 0; jj < 8; jj++) {
        float v0 = __shfl_sync(~0u, a4.x, jj);
        float v1 = __shfl_sync(~0u, a4.y, jj);
        float v2 = __shfl_sync(~0u, a4.z, jj);
        float v3 = __shfl_sync(~0u, a4.w, jj);
        h2 = fmaf(v0, s_w2b[(4 * jj + 0) * 32 + lane], h2);
        h2 = fmaf(v1, s_w2b[(4 * jj + 1) * 32 + lane], h2);
        h2 = fmaf(v2, s_w2b[(4 * jj + 2) * 32 + lane], h2);
        h2 = fmaf(v3, s_w2b[(4 * jj + 3) * 32 + lane], h2);
    }
    float s0 = h2 * __ldg(ws + lane);
    float s1 = h2 * __ldg(ws + 32 + lane);
#pragma unroll
    for (int o = 16; o > 0; o >>= 1) {
        s0 += __shfl_down_sync(~0u, s0, o);
        s1 += __shfl_down_sync(~0u, s1, o);
    }
    if (lane == 0) d_sc[node] = make_float2(s0, s1);
}

// k5: out[i] = sigmoid(s0[c0] + s1[c1] + bs).  2 candidates per thread.
__global__ void k5_score(const int* __restrict__ cand, const float* __restrict__ bs,
                         float* __restrict__ out, int C) {
    int i = blockIdx.x * blockDim.x + threadIdx.x;
    int npair = C >> 1;
    float b = __ldg(bs);
    if (i < npair) {
        int4 c = __ldg((const int4*)cand + i);
        float z0 = d_sc[c.x].x + d_sc[c.y].y + b;
        float z1 = d_sc[c.z].x + d_sc[c.w].y + b;
        ((float2*)out)[i] = make_float2(1.f / (1.f + __expf(-z0)),
                                        1.f / (1.f + __expf(-z1)));
    }
    if ((C & 1) && i == 0) {
        int2 ce = __ldg((const int2*)cand + (C - 1));
        float z = d_sc[ce.x].x + d_sc[ce.y].y + b;
        out[C - 1] = 1.f / (1.f + __expf(-z));
    }
}

extern "C" void kernel_launch(void* const* d_in, const int* in_sizes, int n_in,
                              void* d_out, int out_size) {
    const float* x    = (const float*)d_in[0];
    const int*   ei   = (const int*)d_in[1];
    const int*   cand = (const int*)d_in[2];
    const float* w1a = (const float*)d_in[3];
    const float* b1a = (const float*)d_in[4];
    const float* w2a = (const float*)d_in[5];
    const float* b2a = (const float*)d_in[6];
    const float* w1b = (const float*)d_in[7];
    const float* b1b = (const float*)d_in[8];
    const float* w2b = (const float*)d_in[9];
    const float* b2b = (const float*)d_in[10];
    const float* ws  = (const float*)d_in[11];
    const float* bs  = (const float*)d_in[12];

    int N = in_sizes[0] / 7;
    int E = in_sizes[1] / 2;
    int C = in_sizes[2] / 2;
    float* out = (float*)d_out;
    int NB = (N + SCAN_CHUNK - 1) / SCAN_CHUNK;

    kA_init <<<(N + 255) / 256, 256>>>(x, N);
    kH_hist <<<(E + 255) / 256, 256>>>(ei, E);
    kS1     <<<NB, 512>>>(N);
    kS2     <<<1, 1>>>(NB, N);
    kS3     <<<NB, 512>>>(N);
    kP_place<<<(E + 255) / 256, 256>>>(ei, E);
    kE_agg1 <<<(N * 8 + 255) / 256, 256>>>(N);
    k2_mlpA <<<(N + 127) / 128, 128>>>(w1a, b1a, w2a, b2a, w1b, N);
    kF_agg2_mlpB<<<(N + 7) / 8, 256>>>(b1b, w2b, b2b, ws, N);
    k5_score<<<((C >> 1) + 255) / 256, 256>>>(cand, bs, out, C);
}

// round 11
// speedup vs baseline: 1.2549x; 1.0368x over previous
#include <cuda_runtime.h>
#include <cuda_fp16.h>

#define MAXN 100000
#define EMAX 6400000
#define SCAN_CHUNK 2048   // 512 threads x int4
#define MAXBLK 64

// Static scratch
__device__ __half d_x8h[MAXN * 8];    // x padded to 8, fp16 (16B rows)
__device__ float  d_agg1[MAXN * 8];   // x + sum x[src], fp32
__device__ __half d_g2[MAXN * 32];    // g = h_A @ w1b, fp16 (64B rows)
__device__ int    d_deg[MAXN];
__device__ int    d_off[MAXN + 4];    // exclusive prefix; d_off[N] = E
__device__ int    d_rank[EMAX];       // edge's rank within its dst bucket
__device__ int    d_srcs[EMAX];       // CSR: sources grouped by dst
__device__ int    d_bsum[MAXBLK];
__device__ float2 d_sc[MAXN];

__device__ __forceinline__ unsigned long long pack2(float lo, float hi) {
    unsigned long long r;
    asm("mov.b64 %0, {%1, %2};" : "=l"(r) : "f"(lo), "f"(hi));
    return r;
}
__device__ __forceinline__ void unpack2(unsigned long long v, float& lo, float& hi) {
    asm("mov.b64 {%0, %1}, %2;" : "=f"(lo), "=f"(hi) : "l"(v));
}
__device__ __forceinline__ void fma2(unsigned long long& acc, unsigned long long a,
                                     unsigned long long b) {
    asm("fma.rn.f32x2 %0, %1, %2, %0;" : "+l"(acc) : "l"(a), "l"(b));
}

// kA: pad x into d_x8h (fp16), zero deg
__global__ void kA_init(const float* __restrict__ x, int N) {
    int n = blockIdx.x * blockDim.x + threadIdx.x;
    if (n >= N) return;
    const float* xr = x + (size_t)n * 7;
    half2 h01 = __floats2half2_rn(__ldg(xr), __ldg(xr + 1));
    half2 h23 = __floats2half2_rn(__ldg(xr + 2), __ldg(xr + 3));
    half2 h45 = __floats2half2_rn(__ldg(xr + 4), __ldg(xr + 5));
    half2 h67 = __floats2half2_rn(__ldg(xr + 6), 0.f);
    uint4 pk;
    pk.x = *(unsigned*)&h01; pk.y = *(unsigned*)&h23;
    pk.z = *(unsigned*)&h45; pk.w = *(unsigned*)&h67;
    *(uint4*)(d_x8h + (size_t)n * 8) = pk;
    d_deg[n] = 0;
}

// kH: histogram + per-edge rank (coalesced store), 1 edge/thread
__global__ void kH_hist(const int* __restrict__ ei, int E) {
    int e = blockIdx.x * blockDim.x + threadIdx.x;
    if (e >= E) return;
    int d = __ldg(ei + E + e);
    d_rank[e] = atomicAdd(&d_deg[d], 1);
}

// kS1: per-block sums of deg
__global__ void __launch_bounds__(512) kS1(int N) {
    __shared__ int s_w[16];
    int tid = threadIdx.x;
    int base = blockIdx.x * SCAN_CHUNK + tid * 4;
    int4 v = make_int4(0, 0, 0, 0);
    if (base < N) v = *(const int4*)(d_deg + base);
    int sum = v.x + v.y + v.z + v.w;
#pragma unroll
    for (int o = 16; o > 0; o >>= 1) sum += __shfl_down_sync(~0u, sum, o);
    if ((tid & 31) == 0) s_w[tid >> 5] = sum;
    __syncthreads();
    if (tid < 16) {
        int t = s_w[tid];
#pragma unroll
        for (int o = 8; o > 0; o >>= 1) t += __shfl_down_sync(0xffffu, t, o);
        if (tid == 0) d_bsum[blockIdx.x] = t;
    }
}

// kS3: block-level exclusive scan; block prefix computed locally from d_bsum.
__global__ void __launch_bounds__(512) kS3(int N, int NB) {
    __shared__ int s_w[16];
    __shared__ int s_pref[2];   // [0]=prefix before this block, [1]=grand total
    int tid = threadIdx.x;
    int lane = tid & 31, wid = tid >> 5;
    int b = blockIdx.x;

    if (tid < 64) {   // two warps' worth of bsum entries (NB <= 64)
        int mine = (tid < NB) ? d_bsum[tid] : 0;
        int pre = (tid < b) ? mine : 0;
#pragma unroll
        for (int o = 16; o > 0; o >>= 1) {
            pre  += __shfl_down_sync(~0u, pre, o);
            mine += __shfl_down_sync(~0u, mine, o);
        }
        if (lane == 0) {
            if (tid == 0) { s_pref[0] = pre; s_pref[1] = mine; }
            else { atomicAdd(&s_pref[0], pre); atomicAdd(&s_pref[1], mine); }
        }
    }
    // NOTE: tid 0 and tid 32 both write/add — init order: tid0 stores, tid32 adds.
    // Guard with syncthreads before and after the atomic adds:
    __syncthreads();

    int base = b * SCAN_CHUNK + tid * 4;
    int4 v = make_int4(0, 0, 0, 0);
    if (base < N) v = *(const int4*)(d_deg + base);
    int t1 = v.x + v.y, t2 = t1 + v.z, tot = t2 + v.w;
    int scan = tot;
#pragma unroll
    for (int o = 1; o < 32; o <<= 1) {
        int nv = __shfl_up_sync(~0u, scan, o);
        if (lane >= o) scan += nv;
    }
    if (lane == 31) s_w[wid] = scan;
    __syncthreads();
    if (wid == 0 && lane < 16) {
        int w = s_w[lane];
#pragma unroll
        for (int o = 1; o < 16; o <<= 1) {
            int nv = __shfl_up_sync(0xffffu, w, o);
            if (lane >= o) w += nv;
        }
        s_w[lane] = w;
    }
    __syncthreads();
    int excl = scan - tot + (wid > 0 ? s_w[wid - 1] : 0) + s_pref[0];
    if (base < N)
        *(int4*)(d_off + base) = make_int4(excl, excl + v.x, excl + t1, excl + t2);
    if (b == NB - 1 && tid == 0) d_off[N] = s_pref[1];
}

// kP: place srcs into CSR (no atomics), 1 edge/thread
__global__ void kP_place(const int* __restrict__ ei, int E) {
    int e = blockIdx.x * blockDim.x + threadIdx.x;
    if (e >= E) return;
    int s = __ldg(ei + e);
    int d = __ldg(ei + E + e);
    d_srcs[__ldg(d_off + d) + d_rank[e]] = s;
}

// kE: agg1[n] = x8h[n] + sum x8h[src] (fp32 accum).  8 lanes/node, 4 nodes/warp.
__global__ void __launch_bounds__(256) kE_agg1(int N) {
    int tid = blockIdx.x * blockDim.x + threadIdx.x;
    int node = tid >> 3;
    int j = tid & 7;
    if (node >= N) return;
    int beg = __ldg(d_off + node), end = __ldg(d_off + node + 1);
    float acc = __half2float(d_x8h[(size_t)node * 8 + j]);
    int i = beg;
    for (; i + 1 < end; i += 2) {
        int s0 = __ldg(d_srcs + i);
        int s1 = __ldg(d_srcs + i + 1);
        acc += __half2float(__ldg(d_x8h + (size_t)s0 * 8 + j));
        acc += __half2float(__ldg(d_x8h + (size_t)s1 * 8 + j));
    }
    if (i < end) acc += __half2float(__ldg(d_x8h + (size_t)__ldg(d_srcs + i) * 8 + j));
    d_agg1[(size_t)node * 8 + j] = acc;
}

// k2: per node: t[7] -> relu(t@w1a+b1a) -> @w2a+b2a -> relu -> @w1b = g[32] (fp16 out)
// Rank-1 updates use packed fma.rn.f32x2 (2x FFMA throughput, full fp32 precision).
__global__ void __launch_bounds__(128) k2_mlpA(
    const float* __restrict__ w1a, const float* __restrict__ b1a,
    const float* __restrict__ w2a, const float* __restrict__ b2a,
    const float* __restrict__ w1b, int N) {
    __shared__ float s_w1a[7 * 64];
    __shared__ float s_b1a[64];
    __shared__ float s_w2a[64 * 64];
    __shared__ float s_b2a[64];
    __shared__ float s_w1b[64 * 32];
    for (int i = threadIdx.x; i < 112; i += 128)
        ((float4*)s_w1a)[i] = __ldg((const float4*)w1a + i);
    if (threadIdx.x < 64) { s_b1a[threadIdx.x] = b1a[threadIdx.x]; s_b2a[threadIdx.x] = b2a[threadIdx.x]; }
    for (int i = threadIdx.x; i < 1024; i += 128)
        ((float4*)s_w2a)[i] = __ldg((const float4*)w2a + i);
    for (int i = threadIdx.x; i < 512; i += 128)
        ((float4*)s_w1b)[i] = __ldg((const float4*)w1b + i);
    __syncthreads();

    int n = blockIdx.x * 128 + threadIdx.x;
    if (n >= N) return;

    float tin[7];
    const float* tr = d_agg1 + (size_t)n * 8;
#pragma unroll
    for (int i = 0; i < 7; i++) tin[i] = tr[i];

    unsigned long long acc2[32];   // packed pairs of the 64 hidden accumulators
#pragma unroll
    for (int j = 0; j < 32; j++) acc2[j] = 0ull;

#pragma unroll 1
    for (int k = 0; k < 64; k++) {
        float h = s_b1a[k];
#pragma unroll
        for (int i = 0; i < 7; i++) h = fmaf(tin[i], s_w1a[i * 64 + k], h);
        h = fmaxf(h, 0.f);
        unsigned long long hh = pack2(h, h);
        const unsigned long long* wrow = (const unsigned long long*)(s_w2a + k * 64);
#pragma unroll
        for (int j = 0; j < 32; j++) fma2(acc2[j], hh, wrow[j]);
    }

    unsigned long long g2[16];     // packed pairs of the 32 outputs
#pragma unroll
    for (int j = 0; j < 16; j++) g2[j] = 0ull;

#pragma unroll 1
    for (int j = 0; j < 32; j++) {  // pair of hidden units 2j, 2j+1
        float v0, v1;
        unpack2(acc2[j], v0, v1);
        float h0 = fmaxf(v0 + s_b2a[2 * j], 0.f);
        float h1 = fmaxf(v1 + s_b2a[2 * j + 1], 0.f);
        unsigned long long hh0 = pack2(h0, h0);
        unsigned long long hh1 = pack2(h1, h1);
        const unsigned long long* w0 = (const unsigned long long*)(s_w1b + (2 * j) * 32);
        const unsigned long long* w1 = (const unsigned long long*)(s_w1b + (2 * j + 1) * 32);
#pragma unroll
        for (int m = 0; m < 16; m++) { fma2(g2[m], hh0, w0[m]); fma2(g2[m], hh1, w1[m]); }
    }

    half2 t16[16];
#pragma unroll
    for (int m = 0; m < 16; m++) {
        float lo, hi;
        unpack2(g2[m], lo, hi);
        t16[m] = __floats2half2_rn(lo, hi);
    }
    uint4* dst = (uint4*)(d_g2 + (size_t)n * 32);
#pragma unroll
    for (int q = 0; q < 4; q++) dst[q] = ((uint4*)t16)[q];
}

// kF: warp/node: agg2 = g[n] + sum g[src].  fp16 rows (64B), 4 groups x 8 lanes x uint2.
__global__ void __launch_bounds__(256) kF_agg2_mlpB(
    const float* __restrict__ b1b, const float* __restrict__ w2b,
    const float* __restrict__ b2b, const float* __restrict__ ws, int N) {
    __shared__ float s_w2b[32 * 32];
    ((float4*)s_w2b)[threadIdx.x] = __ldg((const float4*)w2b + threadIdx.x);
    __syncthreads();

    int lane = threadIdx.x & 31;
    int grp = lane >> 3;
    int j = lane & 7;             // uint2 slot -> dims [4j, 4j+4)
    int node = blockIdx.x * 8 + (threadIdx.x >> 5);
    if (node >= N) return;

    int beg = __ldg(d_off + node), end = __ldg(d_off + node + 1);
    float a0 = 0.f, a1 = 0.f, a2 = 0.f, a3 = 0.f;

    if (grp == 0) {
        uint2 r = *(const uint2*)(d_g2 + (size_t)node * 32 + j * 4);
        float2 f0 = __half22float2(*(const half2*)&r.x);
        float2 f1 = __half22float2(*(const half2*)&r.y);
        a0 += f0.x; a1 += f0.y; a2 += f1.x; a3 += f1.y;
    }
#pragma unroll 2
    for (int i = beg + grp; i < end; i += 4) {
        int s = __ldg(d_srcs + i);
        uint2 r = __ldg((const uint2*)(d_g2 + (size_t)s * 32 + j * 4));
        float2 f0 = __half22float2(*(const half2*)&r.x);
        float2 f1 = __half22float2(*(const half2*)&r.y);
        a0 += f0.x; a1 += f0.y; a2 += f1.x; a3 += f1.y;
    }
#pragma unroll
    for (int o = 8; o <= 16; o <<= 1) {
        a0 += __shfl_xor_sync(~0u, a0, o);
        a1 += __shfl_xor_sync(~0u, a1, o);
        a2 += __shfl_xor_sync(~0u, a2, o);
        a3 += __shfl_xor_sync(~0u, a3, o);
    }
    float4 bb = __ldg((const float4*)b1b + j);
    float4 a4;
    a4.x = fmaxf(a0 + bb.x, 0.f);
    a4.y = fmaxf(a1 + bb.y, 0.f);
    a4.z = fmaxf(a2 + bb.z, 0.f);
    a4.w = fmaxf(a3 + bb.w, 0.f);

    float h2 = __ldg(b2b + lane);
#pragma unroll
    for (int jj = 0; jj < 8; jj++) {
        float v0 = __shfl_sync(~0u, a4.x, jj);
        float v1 = __shfl_sync(~0u, a4.y, jj);
        float v2 = __shfl_sync(~0u, a4.z, jj);
        float v3 = __shfl_sync(~0u, a4.w, jj);
        h2 = fmaf(v0, s_w2b[(4 * jj + 0) * 32 + lane], h2);
        h2 = fmaf(v1, s_w2b[(4 * jj + 1) * 32 + lane], h2);
        h2 = fmaf(v2, s_w2b[(4 * jj + 2) * 32 + lane], h2);
        h2 = fmaf(v3, s_w2b[(4 * jj + 3) * 32 + lane], h2);
    }
    float s0 = h2 * __ldg(ws + lane);
    float s1 = h2 * __ldg(ws + 32 + lane);
#pragma unroll
    for (int o = 16; o > 0; o >>= 1) {
        s0 += __shfl_down_sync(~0u, s0, o);
        s1 += __shfl_down_sync(~0u, s1, o);
    }
    if (lane == 0) d_sc[node] = make_float2(s0, s1);
}

// k5: out[i] = sigmoid(s0[c0] + s1[c1] + bs).  2 candidates per thread.
__global__ void k5_score(const int* __restrict__ cand, const float* __restrict__ bs,
                         float* __restrict__ out, int C) {
    int i = blockIdx.x * blockDim.x + threadIdx.x;
    int npair = C >> 1;
    float b = __ldg(bs);
    if (i < npair) {
        int4 c = __ldg((const int4*)cand + i);
        float z0 = d_sc[c.x].x + d_sc[c.y].y + b;
        float z1 = d_sc[c.z].x + d_sc[c.w].y + b;
        ((float2*)out)[i] = make_float2(1.f / (1.f + __expf(-z0)),
                                        1.f / (1.f + __expf(-z1)));
    }
    if ((C & 1) && i == 0) {
        int2 ce = __ldg((const int2*)cand + (C - 1));
        float z = d_sc[ce.x].x + d_sc[ce.y].y + b;
        out[C - 1] = 1.f / (1.f + __expf(-z));
    }
}

extern "C" void kernel_launch(void* const* d_in, const int* in_sizes, int n_in,
                              void* d_out, int out_size) {
    const float* x    = (const float*)d_in[0];
    const int*   ei   = (const int*)d_in[1];
    const int*   cand = (const int*)d_in[2];
    const float* w1a = (const float*)d_in[3];
    const float* b1a = (const float*)d_in[4];
    const float* w2a = (const float*)d_in[5];
    const float* b2a = (const float*)d_in[6];
    const float* w1b = (const float*)d_in[7];
    const float* b1b = (const float*)d_in[8];
    const float* w2b = (const float*)d_in[9];
    const float* b2b = (const float*)d_in[10];
    const float* ws  = (const float*)d_in[11];
    const float* bs  = (const float*)d_in[12];

    int N = in_sizes[0] / 7;
    int E = in_sizes[1] / 2;
    int C = in_sizes[2] / 2;
    float* out = (float*)d_out;
    int NB = (N + SCAN_CHUNK - 1) / SCAN_CHUNK;

    kA_init <<<(N + 255) / 256, 256>>>(x, N);
    kH_hist <<<(E + 255) / 256, 256>>>(ei, E);
    kS1     <<<NB, 512>>>(N);
    kS3     <<<NB, 512>>>(N, NB);
    kP_place<<<(E + 255) / 256, 256>>>(ei, E);
    kE_agg1 <<<(N * 8 + 255) / 256, 256>>>(N);
    k2_mlpA <<<(N + 127) / 128, 128>>>(w1a, b1a, w2a, b2a, w1b, N);
    kF_agg2_mlpB<<<(N + 7) / 8, 256>>>(b1b, w2b, b2b, ws, N);
    k5_score<<<((C >> 1) + 255) / 256, 256>>>(cand, bs, out, C);
}